// round 4
// baseline (speedup 1.0000x reference)
#include <cuda_runtime.h>
#include <stdint.h>

// Problem constants (fixed by the reference: B=4, S=4096, D=2, 3 RK2 steps)
#define BB    4
#define SS    4096
#define WPR   (SS / 32)          // 128 bitmask words per row
#define NWRDS (BB * SS * WPR)    // 2,097,152 words total (8 MB)
#define DT_F      0.1f
#define HALF_DT_F 0.05f
#define EPS_F     1e-8f

// Force-kernel tiling: T threads cooperate on one row, ROWS rows per block.
#define T_PER_ROW 8
#define ROWS_PB   32
#define WPT       (WPR / T_PER_ROW)   // 16 words per thread = 4 uint4

// ---- scratch (static device globals; no runtime allocation) ----
__device__ __align__(16) uint32_t g_bits[NWRDS];   // 8 MB bitmask
__device__ __align__(16) float2   g_p[BB * SS];    // state after each full step
__device__ __align__(16) float2   g_star[BB * SS]; // psi_star
__device__ __align__(16) float2   g_k1[BB * SS];   // k1
__device__              float     g_r[BB * SS];    // per-row radius at step start

// ============================================================================
// 1) Compress dense fp32 0/1 mask -> bitmask via warp ballots.
//    Each warp produces 8 words per loop iteration (8 independent 128B loads
//    in flight -> MLP=8 hides DRAM latency; kernel is HBM-bandwidth-bound).
// ============================================================================
__global__ void compress_kernel(const float* __restrict__ mask) {
    const int lane   = threadIdx.x & 31;
    const int warp   = (blockIdx.x * blockDim.x + threadIdx.x) >> 5;
    const int nwarps = (gridDim.x * blockDim.x) >> 5;

    for (size_t w = (size_t)warp * 8; w < (size_t)NWRDS; w += (size_t)nwarps * 8) {
        // 8 independent, perfectly coalesced 128B loads
        float v0 = mask[(w + 0) * 32 + lane];
        float v1 = mask[(w + 1) * 32 + lane];
        float v2 = mask[(w + 2) * 32 + lane];
        float v3 = mask[(w + 3) * 32 + lane];
        float v4 = mask[(w + 4) * 32 + lane];
        float v5 = mask[(w + 5) * 32 + lane];
        float v6 = mask[(w + 6) * 32 + lane];
        float v7 = mask[(w + 7) * 32 + lane];

        unsigned b0 = __ballot_sync(0xFFFFFFFFu, v0 != 0.0f);
        unsigned b1 = __ballot_sync(0xFFFFFFFFu, v1 != 0.0f);
        unsigned b2 = __ballot_sync(0xFFFFFFFFu, v2 != 0.0f);
        unsigned b3 = __ballot_sync(0xFFFFFFFFu, v3 != 0.0f);
        unsigned b4 = __ballot_sync(0xFFFFFFFFu, v4 != 0.0f);
        unsigned b5 = __ballot_sync(0xFFFFFFFFu, v5 != 0.0f);
        unsigned b6 = __ballot_sync(0xFFFFFFFFu, v6 != 0.0f);
        unsigned b7 = __ballot_sync(0xFFFFFFFFu, v7 != 0.0f);

        if (lane == 0) {
            uint4* dst = reinterpret_cast<uint4*>(g_bits + w);  // w % 8 == 0 -> 32B aligned
            dst[0] = make_uint4(b0, b1, b2, b3);
            dst[1] = make_uint4(b4, b5, b6, b7);
        }
    }
}

// ============================================================================
// Force helper: sum_{j : M[row][j]=1} sp[j]  (sparse scan of the bitmask row)
// T_PER_ROW lanes split the 128 words; shfl-reduce leaves the sum on lane t==0.
// ============================================================================
__device__ __forceinline__ void accum_word(uint32_t w, int base,
                                           const float2* __restrict__ sp,
                                           float& ax, float& ay) {
    while (w) {
        int c = __ffs(w) - 1;
        w &= (w - 1);
        float2 v = sp[base + c];
        ax += v.x;
        ay += v.y;
    }
}

__device__ __forceinline__ void row_force(const float2* __restrict__ sp,
                                          int b, int row, int t,
                                          float& ax, float& ay) {
    const uint4* wr = reinterpret_cast<const uint4*>(
                          g_bits + (size_t)(b * SS + row) * WPR) + t * (WPT / 4);
    ax = 0.0f; ay = 0.0f;
#pragma unroll
    for (int q = 0; q < WPT / 4; q++) {
        uint4 w4   = wr[q];
        int   base = (t * WPT + q * 4) * 32;
        accum_word(w4.x, base,      sp, ax, ay);
        accum_word(w4.y, base + 32, sp, ax, ay);
        accum_word(w4.z, base + 64, sp, ax, ay);
        accum_word(w4.w, base + 96, sp, ax, ay);
    }
#pragma unroll
    for (int off = T_PER_ROW / 2; off > 0; off >>= 1) {
        ax += __shfl_down_sync(0xFFFFFFFFu, ax, off, T_PER_ROW);
        ay += __shfl_down_sync(0xFFFFFFFFu, ay, off, T_PER_ROW);
    }
}

// ============================================================================
// 2a) stepA: from p -> (r, k1, psi_star).   p_in==nullptr means "use g_p".
// ============================================================================
__global__ void __launch_bounds__(ROWS_PB * T_PER_ROW)
stepA_kernel(const float2* __restrict__ p_in) {
    __shared__ float2 sp[SS];  // full per-batch state, 32 KB
    const int b = blockIdx.y;
    const float2* src2 = p_in ? (p_in + b * SS) : (g_p + b * SS);

    {
        const float4* src = reinterpret_cast<const float4*>(src2);
        float4*       dst = reinterpret_cast<float4*>(sp);
        for (int i = threadIdx.x; i < SS / 2; i += blockDim.x) dst[i] = src[i];
    }
    __syncthreads();

    const int row = blockIdx.x * ROWS_PB + threadIdx.x / T_PER_ROW;
    const int t   = threadIdx.x % T_PER_ROW;

    float ax, ay;
    row_force(sp, b, row, t, ax, ay);

    if (t == 0) {
        const int idx = b * SS + row;
        float2 pi = sp[row];
        float  r  = sqrtf(pi.x * pi.x + pi.y * pi.y);
        float k1x = ax - pi.x;
        float k1y = ay - pi.y;
        float sx  = fmaf(DT_F, k1x, pi.x);
        float sy  = fmaf(DT_F, k1y, pi.y);
        float sn  = sqrtf(sx * sx + sy * sy);
        float sc  = r / (sn + EPS_F);
        g_star[idx] = make_float2(sx * sc, sy * sc);
        g_k1[idx]   = make_float2(k1x, k1y);
        g_r[idx]    = r;
    }
}

// ============================================================================
// 2b) stepB: from (psi_star, k1, p, r) -> p_new.
//     p_old==nullptr -> use g_p.  p_out==nullptr -> write g_p.
// ============================================================================
__global__ void __launch_bounds__(ROWS_PB * T_PER_ROW)
stepB_kernel(const float2* __restrict__ p_old, float2* __restrict__ p_out) {
    __shared__ float2 sp[SS];  // psi_star for this batch
    const int b = blockIdx.y;

    {
        const float4* src = reinterpret_cast<const float4*>(g_star + b * SS);
        float4*       dst = reinterpret_cast<float4*>(sp);
        for (int i = threadIdx.x; i < SS / 2; i += blockDim.x) dst[i] = src[i];
    }
    __syncthreads();

    const int row = blockIdx.x * ROWS_PB + threadIdx.x / T_PER_ROW;
    const int t   = threadIdx.x % T_PER_ROW;

    float ax, ay;
    row_force(sp, b, row, t, ax, ay);

    if (t == 0) {
        const int idx = b * SS + row;
        float2 si = sp[row];
        float k2x = ax - si.x;
        float k2y = ay - si.y;
        float2 k1 = g_k1[idx];
        float2 p  = p_old ? p_old[idx] : g_p[idx];
        float  r  = g_r[idx];
        float nx  = fmaf(HALF_DT_F, k1.x + k2x, p.x);
        float ny  = fmaf(HALF_DT_F, k1.y + k2y, p.y);
        float nn  = sqrtf(nx * nx + ny * ny);
        float sc  = r / (nn + EPS_F);
        float2 res = make_float2(nx * sc, ny * sc);
        if (p_out) p_out[idx] = res;
        else       g_p[idx]   = res;
    }
}

// ============================================================================
// Launch: 1 compression pass + 3 x (stepA, stepB). All graph-capturable.
// ============================================================================
extern "C" void kernel_launch(void* const* d_in, const int* in_sizes, int n_in,
                              void* d_out, int out_size) {
    const float* psi  = (const float*)d_in[0];
    const float* mask = (const float*)d_in[1];
    if (n_in >= 2 && in_sizes[0] > in_sizes[1]) {  // defensive: pick by size
        psi  = (const float*)d_in[1];
        mask = (const float*)d_in[0];
    }

    compress_kernel<<<1184, 256>>>(mask);

    dim3 gridF(SS / ROWS_PB, BB);           // (128, 4) = 512 blocks
    const int tpb = ROWS_PB * T_PER_ROW;    // 256 threads

    // step 1: read psi input directly
    stepA_kernel<<<gridF, tpb>>>((const float2*)psi);
    stepB_kernel<<<gridF, tpb>>>((const float2*)psi, nullptr);
    // step 2: state in g_p
    stepA_kernel<<<gridF, tpb>>>(nullptr);
    stepB_kernel<<<gridF, tpb>>>(nullptr, nullptr);
    // step 3: final result straight into d_out
    stepA_kernel<<<gridF, tpb>>>(nullptr);
    stepB_kernel<<<gridF, tpb>>>(nullptr, (float2*)d_out);

    (void)out_size;
}